// round 3
// baseline (speedup 1.0000x reference)
#include <cuda_runtime.h>

// BoundaryFocalLoss: fused boundary-dilated focal BCE loss, scalar output.
// inputs: d_in[0]=inputs f32 [B*T], d_in[1]=targets i32 [B*T], d_in[2]=mask f32 [B*T]
// out: single f32 = sum(f_loss)/sum(mask)

#define T_LEN   200000
#define B_ROWS  128
#define T4      (T_LEN / 4)
#define NGROUPS (B_ROWS * T4)
#define NBLK    2048
#define NTHR    256

#define ALPHA          0.25f
#define BOUNDARY_W     5.0f
#define LABEL_SMOOTH   0.05f

__device__ double   g_partial_f[NBLK];
__device__ double   g_partial_m[NBLK];
__device__ unsigned g_done_count = 0;

__device__ __forceinline__ float elem_loss(float x, int t, float m, bool bd) {
    float pos      = (t != 0) ? 1.0f : 0.0f;
    float smoothed = fmaf(pos, 1.0f - LABEL_SMOOTH, LABEL_SMOOTH * 0.5f);

    float w = bd ? BOUNDARY_W : 1.0f;

    // adaptive = 1 - |sigmoid(x) - 0.5|  (symmetric in sign of x)
    float ea = __expf(-fabsf(x));          // in (0, 1]
    float inv = __frcp_rn(1.0f + ea);      // = sigmoid(|x|) >= 0.5
    float adaptive = 1.5f - inv;
    w *= adaptive;

    float bce = fmaxf(x, 0.0f) - x * smoothed + __logf(1.0f + ea);
    float pt  = __expf(-bce);
    float alpha_w = (t != 0) ? ALPHA : (1.0f - ALPHA);
    float om = 1.0f - pt;
    return alpha_w * om * om * bce * w * m;
}

__global__ void __launch_bounds__(NTHR)
bfl_main(const float* __restrict__ in, const int* __restrict__ tgt,
         const float* __restrict__ mask, float* __restrict__ out) {
    float acc_f = 0.0f, acc_m = 0.0f;

    for (int g = blockIdx.x * NTHR + threadIdx.x; g < NGROUPS; g += NBLK * NTHR) {
        int b    = g / T4;
        int c0   = (g - b * T4) * 4;
        int base = b * T_LEN;

        const float4 xv = __ldg((const float4*)(in   + base + c0));
        const float4 mv = __ldg((const float4*)(mask + base + c0));
        const int4   tv = __ldg((const int4*)  (tgt  + base + c0));

        // neighbor targets: vector loads with exact clamped fallback at row edges
        int4 pv, nv;
        if (c0 >= 4) {
            pv = __ldg((const int4*)(tgt + base + c0 - 4));
        } else {  // c0 == 0: all clamped indices are 0 -> tgt[base] == tv.x
            pv = make_int4(tv.x, tv.x, tv.x, tv.x);
        }
        if (c0 + 8 <= T_LEN) {
            nv = __ldg((const int4*)(tgt + base + c0 + 4));
        } else {  // c0 == T_LEN-4: clamped to last element == tv.w
            nv = make_int4(tv.w, tv.w, tv.w, tv.w);
        }

        int arr[11] = {pv.x, pv.y, pv.z, pv.w, tv.x, tv.y, tv.z, tv.w, nv.x, nv.y, nv.z};
        unsigned dm = 0;
        #pragma unroll
        for (int j = 1; j < 11; j++)
            dm |= ((unsigned)(arr[j] != arr[j - 1])) << j;

        // boundary for element k (col c0+k): any transition in cols [c0+k-3, c0+k+3]
        // transition at col c0-4+j corresponds to bit j => bits (k+1)..(k+7)
        bool b0 = (dm >> 1) & 0x7F;
        bool b1 = (dm >> 2) & 0x7F;
        bool b2 = (dm >> 3) & 0x7F;
        bool b3 = (dm >> 4) & 0x7F;

        float s;
        s  = elem_loss(xv.x, tv.x, mv.x, b0);
        s += elem_loss(xv.y, tv.y, mv.y, b1);
        s += elem_loss(xv.z, tv.z, mv.z, b2);
        s += elem_loss(xv.w, tv.w, mv.w, b3);

        acc_f += s;
        acc_m += (mv.x + mv.y) + (mv.z + mv.w);
    }

    // block reduction (promote to double only here)
    __shared__ double sf[NTHR];
    __shared__ double sm[NTHR];
    int tid = threadIdx.x;
    sf[tid] = (double)acc_f;
    sm[tid] = (double)acc_m;
    __syncthreads();
    #pragma unroll
    for (int s = NTHR / 2; s > 0; s >>= 1) {
        if (tid < s) { sf[tid] += sf[tid + s]; sm[tid] += sm[tid + s]; }
        __syncthreads();
    }

    __shared__ bool is_last;
    if (tid == 0) {
        g_partial_f[blockIdx.x] = sf[0];
        g_partial_m[blockIdx.x] = sm[0];
        __threadfence();
        unsigned prev = atomicAdd(&g_done_count, 1u);
        is_last = (prev == (unsigned)(NBLK - 1));
    }
    __syncthreads();

    // last block performs the deterministic finalize and resets the counter
    if (is_last) {
        double a = 0.0, b = 0.0;
        for (int i = tid; i < NBLK; i += NTHR) {
            a += g_partial_f[i];
            b += g_partial_m[i];
        }
        sf[tid] = a;
        sm[tid] = b;
        __syncthreads();
        #pragma unroll
        for (int s = NTHR / 2; s > 0; s >>= 1) {
            if (tid < s) { sf[tid] += sf[tid + s]; sm[tid] += sm[tid + s]; }
            __syncthreads();
        }
        if (tid == 0) {
            out[0] = (sm[0] > 0.0) ? (float)(sf[0] / sm[0]) : 0.0f;
            g_done_count = 0;  // reset for next graph replay
        }
    }
}

extern "C" void kernel_launch(void* const* d_in, const int* in_sizes, int n_in,
                              void* d_out, int out_size) {
    const float* in   = (const float*)d_in[0];
    const int*   tgt  = (const int*)d_in[1];
    const float* mask = (const float*)d_in[2];
    float* out = (float*)d_out;
    (void)in_sizes; (void)n_in; (void)out_size;

    bfl_main<<<NBLK, NTHR>>>(in, tgt, mask, out);
}

// round 4
// speedup vs baseline: 1.1422x; 1.1422x over previous
#include <cuda_runtime.h>

// BoundaryFocalLoss: fused boundary-dilated focal BCE loss, scalar output.
// inputs: d_in[0]=inputs f32 [B*T], d_in[1]=targets i32 [B*T] (values 0/1),
//         d_in[2]=mask f32 [B*T].  out: single f32 = sum(f_loss)/sum(mask)

#define T_LEN     200000
#define B_ROWS    128
#define GPR       12500          // groups (16 elems) per row = T_LEN/16
#define NTHR      256
#define GX        49             // ceil(GPR / NTHR)
#define NBLK_TOT  (GX * B_ROWS)  // 6272

__device__ double   g_partial_f[NBLK_TOT];
__device__ double   g_partial_m[NBLK_TOT];
__device__ unsigned g_done_count = 0;

__global__ void __launch_bounds__(NTHR)
bfl_main(const float* __restrict__ in, const int* __restrict__ tgt,
         const float* __restrict__ mask, float* __restrict__ out) {
    int g   = blockIdx.x * NTHR + threadIdx.x;   // group index within row
    int row = blockIdx.y;

    float accf = 0.0f, accm = 0.0f;

    if (g < GPR) {
        int base = row * T_LEN + g * 16;

        // 16 contiguous elements: 4x vec4 of each stream (read-once -> streaming)
        float4 x0 = __ldcs((const float4*)(in + base));
        float4 x1 = __ldcs((const float4*)(in + base + 4));
        float4 x2 = __ldcs((const float4*)(in + base + 8));
        float4 x3 = __ldcs((const float4*)(in + base + 12));
        float4 m0 = __ldcs((const float4*)(mask + base));
        float4 m1 = __ldcs((const float4*)(mask + base + 4));
        float4 m2 = __ldcs((const float4*)(mask + base + 8));
        float4 m3 = __ldcs((const float4*)(mask + base + 12));
        int4 t0 = __ldcs((const int4*)(tgt + base));
        int4 t1 = __ldcs((const int4*)(tgt + base + 4));
        int4 t2 = __ldcs((const int4*)(tgt + base + 8));
        int4 t3 = __ldcs((const int4*)(tgt + base + 12));

        // neighbor targets: 4 before (cols c0-4..c0-1), 3 after (c0+16..c0+18)
        int4 pv, nv;
        if (g > 0)        pv = __ldcs((const int4*)(tgt + base - 4));
        else              pv = make_int4(t0.x, t0.x, t0.x, t0.x);  // clamp: no transition
        if (g < GPR - 1)  nv = __ldcs((const int4*)(tgt + base + 16));
        else              nv = make_int4(t3.w, t3.w, t3.w, t3.w);  // clamp

        // pack 24 target bits: bit j = t[c0-4+j] (targets are 0/1)
        unsigned m =
            (unsigned)pv.x        | ((unsigned)pv.y << 1)  | ((unsigned)pv.z << 2)  | ((unsigned)pv.w << 3)  |
            ((unsigned)t0.x << 4) | ((unsigned)t0.y << 5)  | ((unsigned)t0.z << 6)  | ((unsigned)t0.w << 7)  |
            ((unsigned)t1.x << 8) | ((unsigned)t1.y << 9)  | ((unsigned)t1.z << 10) | ((unsigned)t1.w << 11) |
            ((unsigned)t2.x << 12)| ((unsigned)t2.y << 13) | ((unsigned)t2.z << 14) | ((unsigned)t2.w << 15) |
            ((unsigned)t3.x << 16)| ((unsigned)t3.y << 17) | ((unsigned)t3.z << 18) | ((unsigned)t3.w << 19) |
            ((unsigned)nv.x << 20)| ((unsigned)nv.y << 21) | ((unsigned)nv.z << 22);

        unsigned tm = m ^ (m >> 1);   // tm bit j = transition at col c0-4+j (valid j>=1)

        float xs[16] = {x0.x,x0.y,x0.z,x0.w, x1.x,x1.y,x1.z,x1.w,
                        x2.x,x2.y,x2.z,x2.w, x3.x,x3.y,x3.z,x3.w};
        float ms[16] = {m0.x,m0.y,m0.z,m0.w, m1.x,m1.y,m1.z,m1.w,
                        m2.x,m2.y,m2.z,m2.w, m3.x,m3.y,m3.z,m3.w};

        #pragma unroll
        for (int k = 0; k < 16; k++) {
            float x  = xs[k];
            float mm = ms[k];
            bool  pos = (m >> (k + 4)) & 1u;
            // boundary: any transition in cols [c0+k-3, c0+k+3] -> tm bits k+1..k+7
            bool  bd  = ((tm >> (k + 1)) & 0x7Fu) != 0u;

            float bw  = bd ? 5.0f : 1.0f;
            float ax  = fabsf(x);
            float ea  = __expf(-ax);
            float opea = 1.0f + ea;
            float inv = __frcp_rn(opea);          // sigmoid(|x|)
            float adaptive = 1.5f - inv;          // 1 - |sigmoid(x)-0.5|

            float s   = pos ? 0.975f : 0.025f;    // label-smoothed target
            float aw  = pos ? 0.25f  : 0.75f;     // alpha weight
            float bce = fmaxf(x, 0.0f) - x * s + __logf(opea);
            float pt  = __expf(-bce);
            float om  = 1.0f - pt;

            accf += aw * om * om * bce * (bw * adaptive * mm);
            accm += mm;
        }
    }

    // block reduction in double (deterministic)
    __shared__ double sf[NTHR];
    __shared__ double sm[NTHR];
    int tid = threadIdx.x;
    sf[tid] = (double)accf;
    sm[tid] = (double)accm;
    __syncthreads();
    #pragma unroll
    for (int s = NTHR / 2; s > 0; s >>= 1) {
        if (tid < s) { sf[tid] += sf[tid + s]; sm[tid] += sm[tid + s]; }
        __syncthreads();
    }

    int bflat = blockIdx.y * gridDim.x + blockIdx.x;
    __shared__ bool is_last;
    if (tid == 0) {
        g_partial_f[bflat] = sf[0];
        g_partial_m[bflat] = sm[0];
        __threadfence();
        unsigned prev = atomicAdd(&g_done_count, 1u);
        is_last = (prev == (unsigned)(NBLK_TOT - 1));
    }
    __syncthreads();

    if (is_last) {
        double a = 0.0, b = 0.0;
        for (int i = tid; i < NBLK_TOT; i += NTHR) {
            a += g_partial_f[i];
            b += g_partial_m[i];
        }
        sf[tid] = a;
        sm[tid] = b;
        __syncthreads();
        #pragma unroll
        for (int s = NTHR / 2; s > 0; s >>= 1) {
            if (tid < s) { sf[tid] += sf[tid + s]; sm[tid] += sm[tid + s]; }
            __syncthreads();
        }
        if (tid == 0) {
            out[0] = (sm[0] > 0.0) ? (float)(sf[0] / sm[0]) : 0.0f;
            g_done_count = 0;  // reset for next graph replay
        }
    }
}

extern "C" void kernel_launch(void* const* d_in, const int* in_sizes, int n_in,
                              void* d_out, int out_size) {
    const float* in   = (const float*)d_in[0];
    const int*   tgt  = (const int*)d_in[1];
    const float* mask = (const float*)d_in[2];
    float* out = (float*)d_out;
    (void)in_sizes; (void)n_in; (void)out_size;

    dim3 grid(GX, B_ROWS);
    bfl_main<<<grid, NTHR>>>(in, tgt, mask, out);
}